// round 4
// baseline (speedup 1.0000x reference)
#include <cuda_runtime.h>
#include <math.h>
#include <stdint.h>

#define Bv    8
#define Tv    4096
#define DIN   64
#define DRES  1024
#define NCTA  128
#define ROWS  8        // rows of W per CTA
#define NTH   512      // 16 warps: 4 k-quarter groups x 4 warps (rg x bg)
#define NQ    4
#define CTAS_PER_Q (NCTA / NQ)   // 32

// double-buffered h staging + per-(buf, cta) publication tags
__device__ float g_hbuf[2][Bv][DRES];
__device__ int   g_tag[2][NCTA];

// smem: Hsh[8][1024] + Ush[8][64] + red[2][16][16]
#define SMEM_FLOATS (Bv*DRES + Bv*DIN + 2*16*16)
#define SMEM_BYTES  (SMEM_FLOATS * 4)

__device__ __forceinline__ void cp16(uint32_t dst, const void* src) {
    asm volatile("cp.async.cg.shared.global [%0], [%1], 16;\n" :: "r"(dst), "l"(src));
}
__device__ __forceinline__ void cp_commit() {
    asm volatile("cp.async.commit_group;\n");
}
__device__ __forceinline__ void cp_wait_all() {
    asm volatile("cp.async.wait_group 0;\n" ::: "memory");
}
__device__ __forceinline__ void barn(int id, int cnt) {
    asm volatile("bar.sync %0, %1;" :: "r"(id), "r"(cnt) : "memory");
}
__device__ __forceinline__ int ld_acq(const int* p) {
    int v;
    asm volatile("ld.global.acquire.gpu.b32 %0, [%1];" : "=r"(v) : "l"(p) : "memory");
    return v;
}
__device__ __forceinline__ void st_rlx(int* p, int v) {
    asm volatile("st.global.relaxed.gpu.b32 [%0], %1;" :: "l"(p), "r"(v) : "memory");
}
__device__ __forceinline__ float fast_tanh(float x) {
    float e = __expf(2.0f * x);
    return 1.0f - __fdividef(2.0f, e + 1.0f);
}

__global__ void __launch_bounds__(NTH, 1) esn_kernel(
    const float* __restrict__ u,      // [B, T, DIN]
    const float* __restrict__ w_in,   // [DRES, DIN]
    const float* __restrict__ w,      // [DRES, DRES]
    const float* __restrict__ w_bias, // [DRES]
    float* __restrict__ out)          // [B, T, DRES]
{
    extern __shared__ float smem[];
    float* Hsh = smem;                 // [8][1024]
    float* Ush = Hsh + Bv * DRES;      // [8][64]
    float* red = Ush + Bv * DIN;       // [2][16][16]

    const int tid  = threadIdx.x;
    const int wrp  = tid >> 5;
    const int lane = tid & 31;
    const int q    = wrp >> 2;         // k-quarter group 0..3
    const int wq   = wrp & 3;          // warp within group
    const int rg   = wq >> 1;
    const int bg   = wq & 1;
    const int r0   = rg * 4;
    const int b0   = bg * 4;
    const int cta  = blockIdx.x;
    const int r_base = cta * ROWS;
    const int g    = tid & 127;        // thread index within group

    // ---- W slice in registers for all steps ----
    float4 Wreg[4][2];
    #pragma unroll
    for (int rr = 0; rr < 4; ++rr)
        #pragma unroll
        for (int j = 0; j < 2; ++j)
            Wreg[rr][j] = *(const float4*)(w + (size_t)(r_base + r0 + rr) * DRES
                                             + q * 256 + j * 128 + lane * 4);
    float2 winreg[4];
    if (q == 3) {
        #pragma unroll
        for (int rr = 0; rr < 4; ++rr)
            winreg[rr] = *(const float2*)(w_in + (r_base + r0 + rr) * DIN + lane * 2);
    }

    // combine-stage constants (tid < 64)
    float biasr = 0.f;
    size_t obase = 0;
    int hidx = 0;
    if (tid < 64) {
        int tile = tid >> 4, idx = tid & 15;
        int rl = (tile >> 1) * 4 + (idx >> 2);
        int b  = (tile & 1) * 4 + (idx & 3);
        biasr = w_bias[r_base + rl];
        obase = (size_t)b * Tv * DRES + r_base + rl;
        hidx  = b * DRES + r_base + rl;
    }

    const uint32_t HshA = (uint32_t)__cvta_generic_to_shared(Hsh);
    const uint32_t UshA = (uint32_t)__cvta_generic_to_shared(Ush);

    // reduced-value index this lane will own after the tree reduce
    const int jred = ((lane >> 4) & 1) * 8 + ((lane >> 3) & 1) * 4
                   + ((lane >> 2) & 1) * 2 + ((lane >> 1) & 1);

    for (int t = 0; t < Tv; ++t) {
        // u prefetch (independent of flags) — overlap with tag spin
        if (q == 3) {
            int b = g >> 4, i = (g & 15) * 4;
            cp16(UshA + (b * DIN + i) * 4, u + ((size_t)b * Tv + t) * DIN + i);
        }
        cp_commit();

        if (t > 0) {
            const int buf = (t - 1) & 1;
            // poll warp of group q: lane L watches producer CTA q*32+L
            if (wq == 0) {
                const int* tp = &g_tag[buf][q * CTAS_PER_Q + lane];
                while (ld_acq(tp) < t) { }
            }
            barn(q + 1, 128);              // propagate acquire to group
            // load this group's 8KB H quarter from hbuf (contiguous per batch)
            const float* hsrc = &g_hbuf[buf][0][0];
            #pragma unroll
            for (int v = 0; v < 4; ++v) {
                int f4 = v * 128 + g;
                int b  = f4 >> 6;
                int kk = (f4 & 63) * 4;
                cp16(HshA + (b * DRES + q * 256 + kk) * 4,
                     hsrc + b * DRES + q * 256 + kk);
            }
        }
        cp_commit();
        cp_wait_all();
        barn(q + 1, 128);                  // group-wide smem visibility

        // ---- compute: 4 rows x 4 batches over this warp's k-quarter ----
        float acc[16];
        #pragma unroll
        for (int i = 0; i < 16; ++i) acc[i] = 0.f;

        if (t > 0) {
            #pragma unroll
            for (int j = 0; j < 2; ++j) {
                float4 hv[4];
                #pragma unroll
                for (int bb = 0; bb < 4; ++bb)
                    hv[bb] = *(const float4*)&Hsh[(b0 + bb) * DRES
                                                  + q * 256 + j * 128 + lane * 4];
                #pragma unroll
                for (int rr = 0; rr < 4; ++rr) {
                    const float4 wv = Wreg[rr][j];
                    #pragma unroll
                    for (int bb = 0; bb < 4; ++bb) {
                        float s = acc[rr * 4 + bb];
                        s = fmaf(wv.x, hv[bb].x, s);
                        s = fmaf(wv.y, hv[bb].y, s);
                        s = fmaf(wv.z, hv[bb].z, s);
                        s = fmaf(wv.w, hv[bb].w, s);
                        acc[rr * 4 + bb] = s;
                    }
                }
            }
        }
        if (q == 3) {                      // fold input projection
            float2 uv[4];
            #pragma unroll
            for (int bb = 0; bb < 4; ++bb)
                uv[bb] = *(const float2*)&Ush[(b0 + bb) * DIN + lane * 2];
            #pragma unroll
            for (int rr = 0; rr < 4; ++rr)
                #pragma unroll
                for (int bb = 0; bb < 4; ++bb) {
                    float s = acc[rr * 4 + bb];
                    s = fmaf(winreg[rr].x, uv[bb].x, s);
                    s = fmaf(winreg[rr].y, uv[bb].y, s);
                    acc[rr * 4 + bb] = s;
                }
        }

        // ---- register-halving tree reduce (31 SHFL) ----
        #pragma unroll
        for (int i = 0; i < 16; ++i) acc[i] += __shfl_xor_sync(~0u, acc[i], 16);
        float v8[8];
        #pragma unroll
        for (int i = 0; i < 8; ++i) v8[i] = (lane & 16) ? acc[i + 8] : acc[i];
        #pragma unroll
        for (int i = 0; i < 8; ++i) v8[i] += __shfl_xor_sync(~0u, v8[i], 8);
        float v4[4];
        #pragma unroll
        for (int i = 0; i < 4; ++i) v4[i] = (lane & 8) ? v8[i + 4] : v8[i];
        #pragma unroll
        for (int i = 0; i < 4; ++i) v4[i] += __shfl_xor_sync(~0u, v4[i], 4);
        float v2[2];
        #pragma unroll
        for (int i = 0; i < 2; ++i) v2[i] = (lane & 4) ? v4[i + 2] : v4[i];
        #pragma unroll
        for (int i = 0; i < 2; ++i) v2[i] += __shfl_xor_sync(~0u, v2[i], 2);
        float v1 = (lane & 2) ? v2[1] : v2[0];
        v1 += __shfl_xor_sync(~0u, v1, 1);

        float* redt = red + (t & 1) * 256;
        if (!(lane & 1)) redt[wrp * 16 + jred] = v1;
        __syncthreads();                   // red visible CTA-wide

        // combine quarters, bias + tanh, publish
        if (tid < 64) {
            int tile = tid >> 4, idx = tid & 15;
            float v = redt[(0 * 4 + tile) * 16 + idx]
                    + redt[(1 * 4 + tile) * 16 + idx]
                    + redt[(2 * 4 + tile) * 16 + idx]
                    + redt[(3 * 4 + tile) * 16 + idx];
            v = fast_tanh(v + biasr);
            out[obase + (size_t)t * DRES] = v;
            (&g_hbuf[t & 1][0][0])[hidx] = v;
            barn(6, 64);                   // all 64 h stores issued
            if (tid == 0) {
                __threadfence();           // make them gpu-visible
                st_rlx(&g_tag[t & 1][cta], t + 1);
            }
        }
    }
}

extern "C" void kernel_launch(void* const* d_in, const int* in_sizes, int n_in,
                              void* d_out, int out_size) {
    const float* u      = (const float*)d_in[0];
    const float* w_in   = (const float*)d_in[1];
    const float* w      = (const float*)d_in[2];
    const float* w_bias = (const float*)d_in[3];
    float* out = (float*)d_out;

    void* tagPtr = nullptr;
    cudaGetSymbolAddress(&tagPtr, g_tag);
    cudaMemsetAsync(tagPtr, 0, sizeof(int) * 2 * NCTA, 0);

    cudaFuncSetAttribute(esn_kernel,
                         cudaFuncAttributeMaxDynamicSharedMemorySize, SMEM_BYTES);
    esn_kernel<<<NCTA, NTH, SMEM_BYTES>>>(u, w_in, w, w_bias, out);
}

// round 5
// speedup vs baseline: 1.2472x; 1.2472x over previous
#include <cuda_runtime.h>
#include <math.h>
#include <stdint.h>

#define Bv    8
#define Tv    4096
#define DIN   64
#define DRES  1024
#define NCTA  128
#define ROWS  8
#define NTH   512     // 16 warps: 4 k-quarter groups x (2 row-grp x 2 batch-grp)
#define NQ    4
#define CTAS_PER_Q (NCTA / NQ)

// transposed (k-major) double-buffered h staging: g_hbuf[buf][k][b]
__device__ float g_hbuf[2][DRES][Bv];
// per-(quarter,step) completion counters — address rotates every step
__device__ int   g_flags[NQ * Tv];

__device__ __forceinline__ void barn(int id, int cnt) {
    asm volatile("bar.sync %0, %1;" :: "r"(id), "r"(cnt) : "memory");
}
__device__ __forceinline__ int ld_acq(const int* p) {
    int v;
    asm volatile("ld.global.acquire.gpu.b32 %0, [%1];" : "=r"(v) : "l"(p) : "memory");
    return v;
}
__device__ __forceinline__ uint64_t pack2(float lo, float hi) {
    uint64_t r;
    asm("mov.b64 %0, {%1, %2};" : "=l"(r) : "f"(lo), "f"(hi));
    return r;
}
__device__ __forceinline__ void unpack2(float& lo, float& hi, uint64_t v) {
    asm("mov.b64 {%0, %1}, %2;" : "=f"(lo), "=f"(hi) : "l"(v));
}
__device__ __forceinline__ void fma2(uint64_t& d, uint64_t a, uint64_t b) {
    asm("fma.rn.f32x2 %0, %1, %2, %0;" : "+l"(d) : "l"(a), "l"(b));
}
__device__ __forceinline__ float fast_tanh(float x) {
    float e = __expf(2.0f * x);
    return 1.0f - __fdividef(2.0f, e + 1.0f);
}

__global__ void __launch_bounds__(NTH, 1) esn_kernel(
    const float* __restrict__ u,      // [B, T, DIN]
    const float* __restrict__ w_in,   // [DRES, DIN]
    const float* __restrict__ w,      // [DRES, DRES]
    const float* __restrict__ w_bias, // [DRES]
    float* __restrict__ out)          // [B, T, DRES]
{
    __shared__ float red[2][256];     // double-buffered reduce scratch

    const int tid  = threadIdx.x;
    const int wrp  = tid >> 5;
    const int lane = tid & 31;
    const int q    = wrp >> 2;        // k-quarter group 0..3
    const int wq   = wrp & 3;         // warp within group
    const int rg   = wq >> 1;
    const int bg   = wq & 1;
    const int r0   = rg * 4;          // local row base
    const int b0   = bg * 4;          // batch base
    const int cta  = blockIdx.x;
    const int r_base = cta * ROWS;
    const int myq  = cta >> 5;        // quarter this CTA produces into
    const int kq   = q * 256 + lane;  // base k index (m=0)

    // ---- W as row-paired f32x2 in registers for all steps ----
    uint64_t Wp[8][2];
    #pragma unroll
    for (int m = 0; m < 8; ++m)
        #pragma unroll
        for (int rp = 0; rp < 2; ++rp)
            Wp[m][rp] = pack2(
                w[(size_t)(r_base + r0 + 2*rp    ) * DRES + kq + m*32],
                w[(size_t)(r_base + r0 + 2*rp + 1) * DRES + kq + m*32]);

    float2 winreg[4];
    if (q == 3) {
        #pragma unroll
        for (int rr = 0; rr < 4; ++rr)
            winreg[rr] = *(const float2*)(w_in + (r_base + r0 + rr) * DIN + lane * 2);
    }

    // ---- epilogue constants (warp 0: outputs o0=lane, o1=lane+32) ----
    float bias0 = 0.f, bias1 = 0.f;
    int hoff0 = 0, hoff1 = 0;
    size_t ob0 = 0, ob1 = 0;
    if (tid < 32) {
        int t0 = lane >> 4,      i0 = lane & 15;
        int t1 = 2 + (lane >> 4);
        int rl0 = (t0 >> 1) * 4 + (i0 >> 2), bb0 = (t0 & 1) * 4 + (i0 & 3);
        int rl1 = (t1 >> 1) * 4 + (i0 >> 2), bb1 = (t1 & 1) * 4 + (i0 & 3);
        bias0 = w_bias[r_base + rl0];
        bias1 = w_bias[r_base + rl1];
        hoff0 = (r_base + rl0) * Bv + bb0;
        hoff1 = (r_base + rl1) * Bv + bb1;
        ob0 = (size_t)bb0 * Tv * DRES + r_base + rl0;
        ob1 = (size_t)bb1 * Tv * DRES + r_base + rl1;
    }

    // post-tree-reduce value index owned by this (even) lane
    const int jred = ((lane >> 4) & 1) * 8 + ((lane >> 3) & 1) * 4
                   + ((lane >> 2) & 1) * 2 + ((lane >> 1) & 1);

    for (int t = 0; t < Tv; ++t) {
        // u prefetch to registers (independent of flags; overlaps the spin)
        float2 uv[4];
        if (q == 3) {
            #pragma unroll
            for (int bb = 0; bb < 4; ++bb)
                uv[bb] = __ldcg((const float2*)(u + ((size_t)(b0 + bb) * Tv + t) * DIN
                                                  + lane * 2));
        }

        uint64_t acc[2][4];
        #pragma unroll
        for (int rp = 0; rp < 2; ++rp)
            #pragma unroll
            for (int b = 0; b < 4; ++b) acc[rp][b] = 0ull;

        if (t > 0) {
            if (wq == 0) {                         // group poll warp
                const int* fp = &g_flags[q * Tv + (t - 1)];
                while (ld_acq(fp) < CTAS_PER_Q) { }
            }
            barn(q + 1, 128);                      // propagate acquire to group

            // H quarter direct to registers (k-major, .cg = L2 only)
            const float* hb = &g_hbuf[(t - 1) & 1][0][0];
            float4 h4[8];
            #pragma unroll
            for (int m = 0; m < 8; ++m)
                h4[m] = __ldcg((const float4*)(hb + (size_t)(kq + m * 32) * Bv + b0));

            #pragma unroll
            for (int m = 0; m < 8; ++m) {
                const float* hm = (const float*)&h4[m];
                #pragma unroll
                for (int b = 0; b < 4; ++b) {
                    uint64_t hr = pack2(hm[b], hm[b]);
                    fma2(acc[0][b], Wp[m][0], hr);
                    fma2(acc[1][b], Wp[m][1], hr);
                }
            }
        }

        // unpack to 16 scalars (register renaming — near free)
        float acc16[16];
        #pragma unroll
        for (int rp = 0; rp < 2; ++rp)
            #pragma unroll
            for (int b = 0; b < 4; ++b)
                unpack2(acc16[(2 * rp) * 4 + b], acc16[(2 * rp + 1) * 4 + b], acc[rp][b]);

        if (q == 3) {                              // fold input projection
            #pragma unroll
            for (int rr = 0; rr < 4; ++rr)
                #pragma unroll
                for (int bb = 0; bb < 4; ++bb) {
                    float s = acc16[rr * 4 + bb];
                    s = fmaf(winreg[rr].x, uv[bb].x, s);
                    s = fmaf(winreg[rr].y, uv[bb].y, s);
                    acc16[rr * 4 + bb] = s;
                }
        }

        // ---- register-halving tree reduce (31 SHFL) ----
        #pragma unroll
        for (int i = 0; i < 16; ++i) acc16[i] += __shfl_xor_sync(~0u, acc16[i], 16);
        float v8[8];
        #pragma unroll
        for (int i = 0; i < 8; ++i) v8[i] = (lane & 16) ? acc16[i + 8] : acc16[i];
        #pragma unroll
        for (int i = 0; i < 8; ++i) v8[i] += __shfl_xor_sync(~0u, v8[i], 8);
        float v4[4];
        #pragma unroll
        for (int i = 0; i < 4; ++i) v4[i] = (lane & 8) ? v8[i + 4] : v8[i];
        #pragma unroll
        for (int i = 0; i < 4; ++i) v4[i] += __shfl_xor_sync(~0u, v4[i], 4);
        float v2[2];
        #pragma unroll
        for (int i = 0; i < 2; ++i) v2[i] = (lane & 4) ? v4[i + 2] : v4[i];
        #pragma unroll
        for (int i = 0; i < 2; ++i) v2[i] += __shfl_xor_sync(~0u, v2[i], 2);
        float v1 = (lane & 2) ? v2[1] : v2[0];
        v1 += __shfl_xor_sync(~0u, v1, 1);

        float* redt = &red[t & 1][0];
        if (!(lane & 1)) redt[wrp * 16 + jred] = v1;
        __syncthreads();                           // red visible CTA-wide

        // ---- epilogue: warp 0, 2 outputs per lane ----
        if (tid < 32) {
            float s0 = redt[lane]       + redt[64 + lane]
                     + redt[128 + lane] + redt[192 + lane];
            float s1 = redt[32 + lane]  + redt[96 + lane]
                     + redt[160 + lane] + redt[224 + lane];
            s0 = fast_tanh(s0 + bias0);
            s1 = fast_tanh(s1 + bias1);
            float* hb = &g_hbuf[t & 1][0][0];
            hb[hoff0] = s0;
            hb[hoff1] = s1;
            __syncwarp();
            if (lane == 0) {
                __threadfence();                   // release hbuf stores
                atomicAdd(&g_flags[myq * Tv + t], 1);
            }
            // output stores off the critical path
            out[ob0 + (size_t)t * DRES] = s0;
            out[ob1 + (size_t)t * DRES] = s1;
        }
    }
}

extern "C" void kernel_launch(void* const* d_in, const int* in_sizes, int n_in,
                              void* d_out, int out_size) {
    const float* u      = (const float*)d_in[0];
    const float* w_in   = (const float*)d_in[1];
    const float* w      = (const float*)d_in[2];
    const float* w_bias = (const float*)d_in[3];
    float* out = (float*)d_out;

    void* flagsPtr = nullptr;
    cudaGetSymbolAddress(&flagsPtr, g_flags);
    cudaMemsetAsync(flagsPtr, 0, NQ * Tv * sizeof(int), 0);

    esn_kernel<<<NCTA, NTH>>>(u, w_in, w, w_bias, out);
}

// round 6
// speedup vs baseline: 1.5183x; 1.2173x over previous
#include <cuda_runtime.h>
#include <math.h>
#include <stdint.h>

#define Bv    8
#define Tv    4096
#define DIN   64
#define DRES  1024
#define NCTA  128
#define ROWS  8
#define NTH   512     // 16 warps: 4 k-quarter groups x (2 row-grp x 2 batch-half)
#define NQ    4
#define CTAS_PER_Q (NCTA / NQ)

// h staging: [buf][batch-half][k][4 batches]  (contiguous 16B per k per half)
__device__ float g_hbuf[2][2][DRES][4];
// per-(quarter,step) completion counters — address rotates every step
__device__ int   g_flags[NQ * Tv];

__device__ __forceinline__ void barn(int id, int cnt) {
    asm volatile("bar.sync %0, %1;" :: "r"(id), "r"(cnt) : "memory");
}
__device__ __forceinline__ void bar_arrive(int id, int cnt) {
    asm volatile("bar.arrive %0, %1;" :: "r"(id), "r"(cnt) : "memory");
}
__device__ __forceinline__ int ld_acq(const int* p) {
    int v;
    asm volatile("ld.global.acquire.gpu.b32 %0, [%1];" : "=r"(v) : "l"(p) : "memory");
    return v;
}
__device__ __forceinline__ void red_release_add(int* p, int v) {
    asm volatile("red.release.gpu.global.add.s32 [%0], %1;" :: "l"(p), "r"(v) : "memory");
}
__device__ __forceinline__ uint64_t pack2(float lo, float hi) {
    uint64_t r;
    asm("mov.b64 %0, {%1, %2};" : "=l"(r) : "f"(lo), "f"(hi));
    return r;
}
__device__ __forceinline__ void unpack2(float& lo, float& hi, uint64_t v) {
    asm("mov.b64 {%0, %1}, %2;" : "=f"(lo), "=f"(hi) : "l"(v));
}
__device__ __forceinline__ void fma2(uint64_t& d, uint64_t a, uint64_t b) {
    asm("fma.rn.f32x2 %0, %1, %2, %0;" : "+l"(d) : "l"(a), "l"(b));
}
__device__ __forceinline__ float fast_tanh(float x) {
    float e = __expf(2.0f * x);
    return 1.0f - __fdividef(2.0f, e + 1.0f);
}

__global__ void __launch_bounds__(NTH, 1) esn_kernel(
    const float* __restrict__ u,      // [B, T, DIN]
    const float* __restrict__ w_in,   // [DRES, DIN]
    const float* __restrict__ w,      // [DRES, DRES]
    const float* __restrict__ w_bias, // [DRES]
    float* __restrict__ out)          // [B, T, DRES]
{
    __shared__ float red[2][256];     // double-buffered reduce scratch

    const int tid  = threadIdx.x;
    const int wrp  = tid >> 5;
    const int lane = tid & 31;
    const int q    = wrp >> 2;        // k-quarter group 0..3
    const int wq   = wrp & 3;         // warp within group
    const int rg   = wq >> 1;
    const int bg   = wq & 1;          // batch half (plane index)
    const int r0   = rg * 4;
    const int b0   = bg * 4;
    const int cta  = blockIdx.x;
    const int r_base = cta * ROWS;
    const int myq  = cta >> 5;        // quarter this CTA produces into
    const int kq   = q * 256 + lane;  // base k (m=0)
    const bool is_epi = (wrp < 2);    // q=0, wq=0/1 warps also run the epilogue

    // ---- W as row-paired f32x2 in registers for all steps ----
    uint64_t Wp[8][2];
    #pragma unroll
    for (int m = 0; m < 8; ++m)
        #pragma unroll
        for (int rp = 0; rp < 2; ++rp)
            Wp[m][rp] = pack2(
                w[(size_t)(r_base + r0 + 2*rp    ) * DRES + kq + m*32],
                w[(size_t)(r_base + r0 + 2*rp + 1) * DRES + kq + m*32]);

    float2 winreg[4];
    if (q == 3) {
        #pragma unroll
        for (int rr = 0; rr < 4; ++rr)
            winreg[rr] = *(const float2*)(w_in + (r_base + r0 + rr) * DIN + lane * 2);
    }

    // ---- epilogue constants (tid < 64, one output each) ----
    float biasr = 0.f;
    int hoff = 0;
    size_t ob = 0;
    if (tid < 64) {
        int tile = tid >> 4, idx = tid & 15;
        int rl = (tile >> 1) * 4 + (idx >> 2);
        int bb = (tile & 1) * 4 + (idx & 3);
        biasr = w_bias[r_base + rl];
        hoff  = ((bb >> 2) * DRES + r_base + rl) * 4 + (bb & 3);
        ob    = (size_t)bb * Tv * DRES + r_base + rl;
    }

    // post-tree-reduce value index owned by this (even) lane
    const int jred = ((lane >> 4) & 1) * 8 + ((lane >> 3) & 1) * 4
                   + ((lane >> 2) & 1) * 2 + ((lane >> 1) & 1);

    for (int t = 0; t < Tv; ++t) {
        // u prefetch to registers (independent of flags; overlaps the spin)
        float2 uv[4];
        if (q == 3) {
            #pragma unroll
            for (int bb = 0; bb < 4; ++bb)
                uv[bb] = __ldcg((const float2*)(u + ((size_t)(b0 + bb) * Tv + t) * DIN
                                                  + lane * 2));
        }

        uint64_t acc[2][4];
        #pragma unroll
        for (int rp = 0; rp < 2; ++rp)
            #pragma unroll
            for (int b = 0; b < 4; ++b) acc[rp][b] = 0ull;

        if (t > 0) {
            if (wq == 0) {                         // group poll warp
                const int* fp = &g_flags[q * Tv + (t - 1)];
                while (ld_acq(fp) < CTAS_PER_Q) { }
            }
            barn(q + 1, 128);                      // propagate acquire to group

            // H quarter direct to registers (plane = batch half, full sectors)
            const float* hb = &g_hbuf[(t - 1) & 1][bg][0][0];
            float4 h4[8];
            #pragma unroll
            for (int m = 0; m < 8; ++m)
                h4[m] = __ldcg((const float4*)(hb + (size_t)(kq + m * 32) * 4));

            #pragma unroll
            for (int m = 0; m < 8; ++m) {
                const float* hm = (const float*)&h4[m];
                #pragma unroll
                for (int b = 0; b < 4; ++b) {
                    uint64_t hr = pack2(hm[b], hm[b]);
                    fma2(acc[0][b], Wp[m][0], hr);
                    fma2(acc[1][b], Wp[m][1], hr);
                }
            }
        }

        float acc16[16];
        #pragma unroll
        for (int rp = 0; rp < 2; ++rp)
            #pragma unroll
            for (int b = 0; b < 4; ++b)
                unpack2(acc16[(2 * rp) * 4 + b], acc16[(2 * rp + 1) * 4 + b], acc[rp][b]);

        if (q == 3) {                              // fold input projection
            #pragma unroll
            for (int rr = 0; rr < 4; ++rr)
                #pragma unroll
                for (int bb = 0; bb < 4; ++bb) {
                    float s = acc16[rr * 4 + bb];
                    s = fmaf(winreg[rr].x, uv[bb].x, s);
                    s = fmaf(winreg[rr].y, uv[bb].y, s);
                    acc16[rr * 4 + bb] = s;
                }
        }

        // ---- register-halving tree reduce (31 SHFL) ----
        #pragma unroll
        for (int i = 0; i < 16; ++i) acc16[i] += __shfl_xor_sync(~0u, acc16[i], 16);
        float v8[8];
        #pragma unroll
        for (int i = 0; i < 8; ++i) v8[i] = (lane & 16) ? acc16[i + 8] : acc16[i];
        #pragma unroll
        for (int i = 0; i < 8; ++i) v8[i] += __shfl_xor_sync(~0u, v8[i], 8);
        float v4[4];
        #pragma unroll
        for (int i = 0; i < 4; ++i) v4[i] = (lane & 8) ? v8[i + 4] : v8[i];
        #pragma unroll
        for (int i = 0; i < 4; ++i) v4[i] += __shfl_xor_sync(~0u, v4[i], 4);
        float v2[2];
        #pragma unroll
        for (int i = 0; i < 2; ++i) v2[i] = (lane & 4) ? v4[i + 2] : v4[i];
        #pragma unroll
        for (int i = 0; i < 2; ++i) v2[i] += __shfl_xor_sync(~0u, v2[i], 2);
        float v1 = (lane & 2) ? v2[1] : v2[0];
        v1 += __shfl_xor_sync(~0u, v1, 1);

        float* redt = &red[t & 1][0];
        if (!(lane & 1)) redt[wrp * 16 + jred] = v1;

        // ---- decoupled handoff: producers arrive and run ahead ----
        if (!is_epi) {
            bar_arrive(15, NTH);
            continue;                              // straight to next step
        }
        barn(15, NTH);                             // epilogue warps wait for all STS

        // ---- epilogue: 64 threads, one output each ----
        if (tid < 64) {
            float s = redt[tid] + redt[64 + tid]
                    + redt[128 + tid] + redt[192 + tid];
            s = fast_tanh(s + biasr);
            (&g_hbuf[t & 1][0][0][0])[hoff] = s;
            barn(9, 64);                           // hbuf stores ordered before flag
            if (tid == 0)
                red_release_add(&g_flags[myq * Tv + t], 1);
            out[ob + (size_t)t * DRES] = s;        // off the critical path
        }
    }
}

extern "C" void kernel_launch(void* const* d_in, const int* in_sizes, int n_in,
                              void* d_out, int out_size) {
    const float* u      = (const float*)d_in[0];
    const float* w_in   = (const float*)d_in[1];
    const float* w      = (const float*)d_in[2];
    const float* w_bias = (const float*)d_in[3];
    float* out = (float*)d_out;

    void* flagsPtr = nullptr;
    cudaGetSymbolAddress(&flagsPtr, g_flags);
    cudaMemsetAsync(flagsPtr, 0, NQ * Tv * sizeof(int), 0);

    esn_kernel<<<NCTA, NTH>>>(u, w_in, w, w_bias, out);
}